// round 1
// baseline (speedup 1.0000x reference)
#include <cuda_runtime.h>
#include <cstdint>

#define NPOS  16384
#define SCALEF 0.125f

// -------- scratch (device globals; no allocation allowed) --------
__device__ float g_q[(size_t)NPOS * 512];      //  33.5 MB
__device__ float g_qk[(size_t)NPOS * 2048];    // 134 MB
__device__ float g_ybar[(size_t)NPOS * 2048];  // 134 MB
__device__ float g_o[(size_t)NPOS * 512];      //  33.5 MB

// -------- TF32 helpers --------
__device__ __forceinline__ float f2tf(float x) {
    uint32_t u;
    asm("cvt.rna.tf32.f32 %0, %1;" : "=r"(u) : "f"(x));
    return __uint_as_float(u);
}

__device__ __forceinline__ void mma8(float* d, const uint32_t* a, const uint32_t* b) {
    asm volatile(
        "mma.sync.aligned.m16n8k8.row.col.f32.tf32.tf32.f32 "
        "{%0,%1,%2,%3}, {%4,%5,%6,%7}, {%8,%9}, {%0,%1,%2,%3};"
        : "+f"(d[0]), "+f"(d[1]), "+f"(d[2]), "+f"(d[3])
        : "r"(a[0]), "r"(a[1]), "r"(a[2]), "r"(a[3]), "r"(b[0]), "r"(b[1]));
}

// -------- generic TF32 GEMM: C[m,n] = alpha * sum_k A[m,k]*B[k,n] (+bias[n]) --------
// A is k-contiguous (sAk==1). B has arbitrary (sBk, sBn). C is n-contiguous.
// blockIdx.z batches with per-operand batch strides (for per-head GEMMs).
#define BM 128
#define BN 64
#define BK 32

__global__ __launch_bounds__(128)
void gemm_tf32(const float* __restrict__ A, const float* __restrict__ B,
               float* __restrict__ C, const float* __restrict__ bias,
               int K,
               int sAm, long long aBatch,
               long long sBk, long long sBn, long long bBatch,
               int sCm, long long cBatch, float alpha)
{
    __shared__ float As[BK][BM + 8];
    __shared__ float Bs[BK][BN + 8];

    const int bm = blockIdx.x * BM;
    const int bn = blockIdx.y * BN;
    const int t = threadIdx.x;
    const int lane = t & 31, wid = t >> 5;
    const int g = lane >> 2, tig = lane & 3;
    const int wm = (wid >> 1) * 64, wn = (wid & 1) * 32;

    const float* Ap = A + (long long)blockIdx.z * aBatch + (long long)(bm + t) * sAm;
    const float* Bb = B + (long long)blockIdx.z * bBatch;
    float*       Cb = C + (long long)blockIdx.z * cBatch;

    const bool kfast = (sBk < sBn);   // load B with k fastest when k is contiguous

    float acc[4][4][4];
#pragma unroll
    for (int i = 0; i < 4; i++)
#pragma unroll
        for (int j = 0; j < 4; j++)
#pragma unroll
            for (int q = 0; q < 4; q++) acc[i][j][q] = 0.f;

    float4 pa[8];
    float  pb[16];

    // prefetch first tile
#pragma unroll
    for (int i = 0; i < 8; i++) pa[i] = *(const float4*)(Ap + i * 4);
#pragma unroll
    for (int i = 0; i < 16; i++) {
        int idx = i * 128 + t;
        int k = kfast ? (idx & 31) : (idx >> 6);
        int n = kfast ? (idx >> 5) : (idx & 63);
        pb[i] = Bb[(long long)k * sBk + (long long)(bn + n) * sBn];
    }

    for (int kt = 0; kt < K; kt += BK) {
        // stage (tf32-converted) tile into smem; A stored transposed [k][m]
#pragma unroll
        for (int i = 0; i < 8; i++) {
            As[i * 4 + 0][t] = f2tf(pa[i].x);
            As[i * 4 + 1][t] = f2tf(pa[i].y);
            As[i * 4 + 2][t] = f2tf(pa[i].z);
            As[i * 4 + 3][t] = f2tf(pa[i].w);
        }
#pragma unroll
        for (int i = 0; i < 16; i++) {
            int idx = i * 128 + t;
            int k = kfast ? (idx & 31) : (idx >> 6);
            int n = kfast ? (idx >> 5) : (idx & 63);
            Bs[k][n] = f2tf(pb[i]);
        }
        __syncthreads();

        if (kt + BK < K) {
            const float* Ap2 = Ap + kt + BK;
#pragma unroll
            for (int i = 0; i < 8; i++) pa[i] = *(const float4*)(Ap2 + i * 4);
#pragma unroll
            for (int i = 0; i < 16; i++) {
                int idx = i * 128 + t;
                int k = kfast ? (idx & 31) : (idx >> 6);
                int n = kfast ? (idx >> 5) : (idx & 63);
                pb[i] = Bb[(long long)(kt + BK + k) * sBk + (long long)(bn + n) * sBn];
            }
        }

#pragma unroll
        for (int ks = 0; ks < 4; ks++) {
            const int k0 = ks * 8;
            uint32_t af[4][4], bf[4][2];
#pragma unroll
            for (int mi = 0; mi < 4; mi++) {
                int r = wm + mi * 16 + g;
                af[mi][0] = __float_as_uint(As[k0 + tig][r]);
                af[mi][1] = __float_as_uint(As[k0 + tig][r + 8]);
                af[mi][2] = __float_as_uint(As[k0 + tig + 4][r]);
                af[mi][3] = __float_as_uint(As[k0 + tig + 4][r + 8]);
            }
#pragma unroll
            for (int ni = 0; ni < 4; ni++) {
                int cn = wn + ni * 8 + g;
                bf[ni][0] = __float_as_uint(Bs[k0 + tig][cn]);
                bf[ni][1] = __float_as_uint(Bs[k0 + tig + 4][cn]);
            }
#pragma unroll
            for (int mi = 0; mi < 4; mi++)
#pragma unroll
                for (int ni = 0; ni < 4; ni++)
                    mma8(acc[mi][ni], af[mi], bf[ni]);
        }
        __syncthreads();
    }

    // epilogue
#pragma unroll
    for (int mi = 0; mi < 4; mi++) {
#pragma unroll
        for (int ni = 0; ni < 4; ni++) {
            int r  = bm + wm + mi * 16 + g;
            int cn = bn + wn + ni * 8 + 2 * tig;
            float b0 = bias ? bias[cn] : 0.f;
            float b1 = bias ? bias[cn + 1] : 0.f;
            float2 v0 = make_float2(alpha * acc[mi][ni][0] + b0,
                                    alpha * acc[mi][ni][1] + b1);
            float2 v1 = make_float2(alpha * acc[mi][ni][2] + b0,
                                    alpha * acc[mi][ni][3] + b1);
            *(float2*)(Cb + (long long)r * sCm + cn)       = v0;
            *(float2*)(Cb + (long long)(r + 8) * sCm + cn) = v1;
        }
    }
}

// -------- fused attention core (fp32): dots -> softmax -> ybar, per position --------
// one 128-thread CTA per position p; y[p]:16x256, qk[p]:8x256 in smem.
#define YP 260   // padded row stride (floats) to dodge bank conflicts

__global__ __launch_bounds__(128)
void attn_kernel(const float* __restrict__ y, const float* __restrict__ qk,
                 float* __restrict__ ybar)
{
    __shared__ float ys[16 * YP];
    __shared__ float qs[8 * YP];
    __shared__ float attn_s[128];

    const int p = blockIdx.x;
    const int t = threadIdx.x;
    const float* yg = y + (long long)p * 4096;
    const float* qg = qk + (long long)p * 2048;

#pragma unroll
    for (int i = 0; i < 8; i++) {
        int idx4 = i * 128 + t;                 // float4 index over 16x256
        float4 v = *(const float4*)(yg + idx4 * 4);
        int m = idx4 >> 6, c = (idx4 & 63) * 4;
        *(float4*)(ys + m * YP + c) = v;
    }
#pragma unroll
    for (int i = 0; i < 4; i++) {
        int idx4 = i * 128 + t;                 // float4 index over 8x256
        float4 v = *(const float4*)(qg + idx4 * 4);
        int h = idx4 >> 6, c = (idx4 & 63) * 4;
        *(float4*)(qs + h * YP + c) = v;
    }
    __syncthreads();

    const int h = t >> 4, m = t & 15;           // thread owns (h, m) score

    // dots[h,m] = qk[h,:] . y[m,:]   (SCALE already folded into qk)
    const float4* y4 = (const float4*)(ys + m * YP);
    const float4* q4 = (const float4*)(qs + h * YP);
    float ax = 0.f, ay = 0.f, az = 0.f, aw = 0.f;
#pragma unroll 8
    for (int i = 0; i < 64; i++) {
        float4 a = q4[i], b = y4[i];
        ax = fmaf(a.x, b.x, ax);
        ay = fmaf(a.y, b.y, ay);
        az = fmaf(a.z, b.z, az);
        aw = fmaf(a.w, b.w, aw);
    }
    float dot = (ax + ay) + (az + aw);

    // softmax over the 16 lanes sharing h (lanes [0..15] / [16..31] of each warp)
    float mx = dot;
#pragma unroll
    for (int o = 8; o >= 1; o >>= 1)
        mx = fmaxf(mx, __shfl_xor_sync(0xffffffffu, mx, o));
    float e = __expf(dot - mx);
    float s = e;
#pragma unroll
    for (int o = 8; o >= 1; o >>= 1)
        s += __shfl_xor_sync(0xffffffffu, s, o);
    attn_s[t] = e / s;
    __syncthreads();

    // ybar[h, cc..cc+15] = sum_m attn[h,m] * y[m, cc..cc+15]
    const int cc = (t & 15) << 4;
    float4 r0 = make_float4(0, 0, 0, 0), r1 = r0, r2 = r0, r3 = r0;
#pragma unroll
    for (int mm = 0; mm < 16; mm++) {
        float a = attn_s[(h << 4) | mm];
        const float4* yy = (const float4*)(ys + mm * YP + cc);
        float4 b0 = yy[0], b1 = yy[1], b2 = yy[2], b3 = yy[3];
        r0.x = fmaf(a, b0.x, r0.x); r0.y = fmaf(a, b0.y, r0.y);
        r0.z = fmaf(a, b0.z, r0.z); r0.w = fmaf(a, b0.w, r0.w);
        r1.x = fmaf(a, b1.x, r1.x); r1.y = fmaf(a, b1.y, r1.y);
        r1.z = fmaf(a, b1.z, r1.z); r1.w = fmaf(a, b1.w, r1.w);
        r2.x = fmaf(a, b2.x, r2.x); r2.y = fmaf(a, b2.y, r2.y);
        r2.z = fmaf(a, b2.z, r2.z); r2.w = fmaf(a, b2.w, r2.w);
        r3.x = fmaf(a, b3.x, r3.x); r3.y = fmaf(a, b3.y, r3.y);
        r3.z = fmaf(a, b3.z, r3.z); r3.w = fmaf(a, b3.w, r3.w);
    }
    float* op = ybar + (long long)p * 2048 + (h << 8) + cc;
    ((float4*)op)[0] = r0;
    ((float4*)op)[1] = r1;
    ((float4*)op)[2] = r2;
    ((float4*)op)[3] = r3;
}

// -------- launch --------
extern "C" void kernel_launch(void* const* d_in, const int* in_sizes, int n_in,
                              void* d_out, int out_size)
{
    const float* x     = (const float*)d_in[0];
    const float* y     = (const float*)d_in[1];
    const float* W_q   = (const float*)d_in[2];
    const float* W_kv  = (const float*)d_in[3];
    const float* W_out = (const float*)d_in[4];
    const float* b_out = (const float*)d_in[5];
    float* out = (float*)d_out;

    float *q, *qk, *ybar, *o;
    cudaGetSymbolAddress((void**)&q,    g_q);
    cudaGetSymbolAddress((void**)&qk,   g_qk);
    cudaGetSymbolAddress((void**)&ybar, g_ybar);
    cudaGetSymbolAddress((void**)&o,    g_o);

    dim3 blk(128);

    // K1: q[p, 512] = x[p, 256] @ W_q[256, 512]
    gemm_tf32<<<dim3(128, 8, 1), blk>>>(x, W_q, q, nullptr, 256,
                                        256, 0,   512, 1, 0,   512, 0, 1.0f);

    // K2 (per head h via z): qk[p, h*256+c] = SCALE * sum_d q[p, h*64+d] * W_kv[c, h*64+d]
    gemm_tf32<<<dim3(128, 4, 8), blk>>>(q, W_kv, qk, nullptr, 64,
                                        512, 64,   1, 1024, 64,   2048, 256, SCALEF);

    // K3: dots -> softmax -> ybar (fp32, fused, one CTA per position)
    attn_kernel<<<NPOS, 128>>>(y, qk, ybar);

    // K4 (per head): o[p, h*64+d] = sum_c ybar[p, h*256+c] * W_kv[c, 512 + h*64 + d]
    gemm_tf32<<<dim3(128, 1, 8), blk>>>(ybar, W_kv + 512, o, nullptr, 256,
                                        2048, 256,   1024, 1, 64,   512, 64, 1.0f);

    // K5: out = o[p,512] @ W_out[512,256] + b_out
    gemm_tf32<<<dim3(128, 4, 1), blk>>>(o, W_out, out, b_out, 512,
                                        512, 0,   256, 1, 0,   256, 0, 1.0f);
}

// round 2
// speedup vs baseline: 1.4822x; 1.4822x over previous
#include <cuda_runtime.h>
#include <cstdint>

#define NPOS   16384
#define SCALEF 0.125f

// -------- scratch (device globals; no allocation allowed) --------
__device__ float g_qk[(size_t)NPOS * 2048];    // 134 MB
__device__ float g_ybar[(size_t)NPOS * 2048];  // 134 MB
__device__ float g_wg[256 * 2048];             // 2 MB : SCALE * Wq @ Wk^T  (per head)
__device__ float g_wf[2048 * 256];             // 2 MB : Wv @ W_out        (per head)

// ================= precompute kernels (exact fp32) =================
// Wg[i, h*256+c] = SCALE * sum_d Wq[i, h*64+d] * Wkv[c, h*64+d]
__global__ __launch_bounds__(256)
void wg_kernel(const float* __restrict__ Wq, const float* __restrict__ Wkv,
               float* __restrict__ Wg)
{
    int idx = blockIdx.x * 256 + threadIdx.x;   // 524288 total
    int i = idx >> 11;
    int h = (idx >> 8) & 7;
    int c = idx & 255;
    const float4* a = (const float4*)(Wq  + i * 512  + h * 64);
    const float4* b = (const float4*)(Wkv + c * 1024 + h * 64);
    float s = 0.f;
#pragma unroll
    for (int d = 0; d < 16; d++) {
        float4 u = a[d], v = b[d];
        s += u.x * v.x + u.y * v.y + u.z * v.z + u.w * v.w;
    }
    Wg[idx] = SCALEF * s;
}

// Wf[h*256+c, j] = sum_d Wkv[c, 512 + h*64+d] * W_out[h*64+d, j]
__global__ __launch_bounds__(256)
void wf_kernel(const float* __restrict__ Wkv, const float* __restrict__ Wout,
               float* __restrict__ Wf)
{
    int idx = blockIdx.x * 256 + threadIdx.x;   // 131072 total
    int row = idx >> 6;              // h*256+c
    int j = (idx & 63) * 4;
    int h = row >> 8, c = row & 255;
    const float* wv = Wkv + c * 1024 + 512 + h * 64;
    const float* wo = Wout + h * 64 * 256 + j;
    float4 acc = make_float4(0.f, 0.f, 0.f, 0.f);
#pragma unroll 8
    for (int d = 0; d < 64; d++) {
        float s = wv[d];
        float4 o = *(const float4*)(wo + d * 256);
        acc.x = fmaf(s, o.x, acc.x);
        acc.y = fmaf(s, o.y, acc.y);
        acc.z = fmaf(s, o.z, acc.z);
        acc.w = fmaf(s, o.w, acc.w);
    }
    *(float4*)(Wf + row * 256 + j) = acc;
}

// ================= TF32 GEMM v2: cp.async double-buffer, 256 thr =================
__device__ __forceinline__ float f2tf(float x) {
    uint32_t u;
    asm("cvt.rna.tf32.f32 %0, %1;" : "=r"(u) : "f"(x));
    return __uint_as_float(u);
}

__device__ __forceinline__ void mma8(float* d, const uint32_t* a, const uint32_t* b) {
    asm volatile(
        "mma.sync.aligned.m16n8k8.row.col.f32.tf32.tf32.f32 "
        "{%0,%1,%2,%3}, {%4,%5,%6,%7}, {%8,%9}, {%0,%1,%2,%3};"
        : "+f"(d[0]), "+f"(d[1]), "+f"(d[2]), "+f"(d[3])
        : "r"(a[0]), "r"(a[1]), "r"(a[2]), "r"(a[3]), "r"(b[0]), "r"(b[1]));
}

__device__ __forceinline__ void cpasync16(uint32_t s, const void* g) {
    asm volatile("cp.async.cg.shared.global [%0], [%1], 16;" :: "r"(s), "l"(g));
}

#define BM 128
#define BN 128
#define BK 32
#define ASTR 36     // (BK + 4) floats per A row, [BM][BK]
#define BSTR 132    // (BN + 4) floats per B row, [BK][BN]
#define A_FLOATS (BM * ASTR)   // 4608
#define B_FLOATS (BK * BSTR)   // 4224
#define GEMM_SMEM ((2 * A_FLOATS + 2 * B_FLOATS) * 4)  // 70656 bytes

// C[m,n] = sum_k A[m,k]*B[k,n] (+bias[n]); A k-contig (lda=K), B n-contig, C n-contig.
// M % 128 == 0, N % 128 == 0, K % 32 == 0.
__global__ __launch_bounds__(256, 2)
void gemm2(const float* __restrict__ A, const float* __restrict__ B,
           float* __restrict__ C, const float* __restrict__ bias,
           int K, int lda, int ldb, int ldc)
{
    extern __shared__ float sm[];
    float* As = sm;                        // [2][A_FLOATS]
    float* Bs = sm + 2 * A_FLOATS;         // [2][B_FLOATS]

    const int t = threadIdx.x;
    const int lane = t & 31, wid = t >> 5;
    const int g = lane >> 2, tig = lane & 3;
    const int wm = (wid & 1) * 64;         // 2 warps along M
    const int wn = (wid >> 1) * 32;        // 4 warps along N
    const long long bm = (long long)blockIdx.x * BM;
    const long long bn = (long long)blockIdx.y * BN;

    // cp.async thread mapping
    const int arow = t >> 3, ac4 = t & 7;       // A: 4 chunks, rows arow + 32*i
    const int brow = t >> 5, bc4 = t & 31;      // B: 4 chunks, rows brow + 8*i

    const float* Ag = A + (bm + arow) * lda + ac4 * 4;
    const float* Bg = B + (long long)brow * ldb + bn + bc4 * 4;

    uint32_t as_s[2], bs_s[2];
#pragma unroll
    for (int s = 0; s < 2; s++) {
        as_s[s] = (uint32_t)__cvta_generic_to_shared(As + s * A_FLOATS + arow * ASTR + ac4 * 4);
        bs_s[s] = (uint32_t)__cvta_generic_to_shared(Bs + s * B_FLOATS + brow * BSTR + bc4 * 4);
    }

    float acc[4][4][4];
#pragma unroll
    for (int i = 0; i < 4; i++)
#pragma unroll
        for (int j = 0; j < 4; j++)
#pragma unroll
            for (int q = 0; q < 4; q++) acc[i][j][q] = 0.f;

    const int ntiles = K / BK;

    // prefetch tile 0 -> stage 0
#pragma unroll
    for (int i = 0; i < 4; i++) {
        cpasync16(as_s[0] + i * 32 * ASTR * 4, Ag + (long long)(32 * i) * lda);
        cpasync16(bs_s[0] + i * 8 * BSTR * 4,  Bg + (long long)(8 * i) * ldb);
    }
    asm volatile("cp.async.commit_group;");

    for (int it = 0; it < ntiles; it++) {
        const int buf = it & 1;
        if (it + 1 < ntiles) {
            const int nb = buf ^ 1;
            const long long koff = (long long)(it + 1) * BK;
#pragma unroll
            for (int i = 0; i < 4; i++) {
                cpasync16(as_s[nb] + i * 32 * ASTR * 4, Ag + (long long)(32 * i) * lda + koff);
                cpasync16(bs_s[nb] + i * 8 * BSTR * 4,  Bg + (koff + 8 * i) * ldb);
            }
            asm volatile("cp.async.commit_group;");
            asm volatile("cp.async.wait_group 1;");
        } else {
            asm volatile("cp.async.wait_group 0;");
        }
        __syncthreads();

        const float* as = As + buf * A_FLOATS;
        const float* bs = Bs + buf * B_FLOATS;
#pragma unroll
        for (int ks = 0; ks < 4; ks++) {
            const int k0 = ks * 8;
            uint32_t af[4][4], bf[4][2];
#pragma unroll
            for (int mi = 0; mi < 4; mi++) {
                const int r = wm + mi * 16 + g;
                af[mi][0] = __float_as_uint(f2tf(as[r * ASTR + k0 + tig]));
                af[mi][1] = __float_as_uint(f2tf(as[(r + 8) * ASTR + k0 + tig]));
                af[mi][2] = __float_as_uint(f2tf(as[r * ASTR + k0 + tig + 4]));
                af[mi][3] = __float_as_uint(f2tf(as[(r + 8) * ASTR + k0 + tig + 4]));
            }
#pragma unroll
            for (int ni = 0; ni < 4; ni++) {
                const int cn = wn + ni * 8 + g;
                bf[ni][0] = __float_as_uint(f2tf(bs[(k0 + tig) * BSTR + cn]));
                bf[ni][1] = __float_as_uint(f2tf(bs[(k0 + tig + 4) * BSTR + cn]));
            }
#pragma unroll
            for (int mi = 0; mi < 4; mi++)
#pragma unroll
                for (int ni = 0; ni < 4; ni++)
                    mma8(acc[mi][ni], af[mi], bf[ni]);
        }
        __syncthreads();
    }

    // epilogue
#pragma unroll
    for (int mi = 0; mi < 4; mi++) {
#pragma unroll
        for (int ni = 0; ni < 4; ni++) {
            const long long r = bm + wm + mi * 16 + g;
            const int cn = (int)bn + wn + ni * 8 + 2 * tig;
            float b0 = bias ? bias[cn] : 0.f;
            float b1 = bias ? bias[cn + 1] : 0.f;
            float2 v0 = make_float2(acc[mi][ni][0] + b0, acc[mi][ni][1] + b1);
            float2 v1 = make_float2(acc[mi][ni][2] + b0, acc[mi][ni][3] + b1);
            *(float2*)(C + r * ldc + cn)       = v0;
            *(float2*)(C + (r + 8) * ldc + cn) = v1;
        }
    }
}

// ================= fused attention core (fp32) =================
// per position: dots = qk . y^T -> softmax -> ybar = attn @ y
#define YP 260

__global__ __launch_bounds__(128)
void attn2(const float* __restrict__ y, const float* __restrict__ qk,
           float* __restrict__ ybar)
{
    __shared__ float ys[16 * YP];
    __shared__ float qs[8 * YP];
    __shared__ float attn_s[128];   // layout [m][h]: attn_s[m*8+h]

    const int p = blockIdx.x;
    const int t = threadIdx.x;
    const float* yg = y  + (long long)p * 4096;
    const float* qg = qk + (long long)p * 2048;

#pragma unroll
    for (int i = 0; i < 8; i++) {
        int idx4 = i * 128 + t;
        float4 v = *(const float4*)(yg + idx4 * 4);
        int m = idx4 >> 6, c = (idx4 & 63) * 4;
        *(float4*)(ys + m * YP + c) = v;
    }
#pragma unroll
    for (int i = 0; i < 4; i++) {
        int idx4 = i * 128 + t;
        float4 v = *(const float4*)(qg + idx4 * 4);
        int h = idx4 >> 6, c = (idx4 & 63) * 4;
        *(float4*)(qs + h * YP + c) = v;
    }
    __syncthreads();

    const int h = t >> 4, m = t & 15;

    // dots[h,m] = qk[h,:] . y[m,:]
    const float4* y4 = (const float4*)(ys + m * YP);
    const float4* q4 = (const float4*)(qs + h * YP);
    float ax = 0.f, ay = 0.f, az = 0.f, aw = 0.f;
#pragma unroll 8
    for (int i = 0; i < 64; i++) {
        float4 a = q4[i], b = y4[i];
        ax = fmaf(a.x, b.x, ax);
        ay = fmaf(a.y, b.y, ay);
        az = fmaf(a.z, b.z, az);
        aw = fmaf(a.w, b.w, aw);
    }
    float dot = (ax + ay) + (az + aw);

    // softmax over the 16 lanes sharing h
    float mx = dot;
#pragma unroll
    for (int o = 8; o >= 1; o >>= 1)
        mx = fmaxf(mx, __shfl_xor_sync(0xffffffffu, mx, o));
    float e = __expf(dot - mx);
    float s = e;
#pragma unroll
    for (int o = 8; o >= 1; o >>= 1)
        s += __shfl_xor_sync(0xffffffffu, s, o);
    attn_s[m * 8 + h] = e / s;
    __syncthreads();

    // ybar: thread owns 2 c-columns (c0 = 2t) across ALL 8 heads; y read once
    const int c0 = 2 * t;
    float2 acc[8];
#pragma unroll
    for (int i = 0; i < 8; i++) acc[i] = make_float2(0.f, 0.f);

#pragma unroll
    for (int mm = 0; mm < 16; mm++) {
        float4 a0 = *(const float4*)(attn_s + mm * 8);
        float4 a1 = *(const float4*)(attn_s + mm * 8 + 4);
        float2 yv = *(const float2*)(ys + mm * YP + c0);
        acc[0].x = fmaf(a0.x, yv.x, acc[0].x); acc[0].y = fmaf(a0.x, yv.y, acc[0].y);
        acc[1].x = fmaf(a0.y, yv.x, acc[1].x); acc[1].y = fmaf(a0.y, yv.y, acc[1].y);
        acc[2].x = fmaf(a0.z, yv.x, acc[2].x); acc[2].y = fmaf(a0.z, yv.y, acc[2].y);
        acc[3].x = fmaf(a0.w, yv.x, acc[3].x); acc[3].y = fmaf(a0.w, yv.y, acc[3].y);
        acc[4].x = fmaf(a1.x, yv.x, acc[4].x); acc[4].y = fmaf(a1.x, yv.y, acc[4].y);
        acc[5].x = fmaf(a1.y, yv.x, acc[5].x); acc[5].y = fmaf(a1.y, yv.y, acc[5].y);
        acc[6].x = fmaf(a1.z, yv.x, acc[6].x); acc[6].y = fmaf(a1.z, yv.y, acc[6].y);
        acc[7].x = fmaf(a1.w, yv.x, acc[7].x); acc[7].y = fmaf(a1.w, yv.y, acc[7].y);
    }

    float* op = ybar + (long long)p * 2048 + c0;
#pragma unroll
    for (int hh = 0; hh < 8; hh++)
        *(float2*)(op + hh * 256) = acc[hh];
}

// ================= launch =================
extern "C" void kernel_launch(void* const* d_in, const int* in_sizes, int n_in,
                              void* d_out, int out_size)
{
    const float* x     = (const float*)d_in[0];
    const float* y     = (const float*)d_in[1];
    const float* W_q   = (const float*)d_in[2];
    const float* W_kv  = (const float*)d_in[3];
    const float* W_out = (const float*)d_in[4];
    const float* b_out = (const float*)d_in[5];
    float* out = (float*)d_out;

    float *qk, *ybar, *wg, *wf;
    cudaGetSymbolAddress((void**)&qk,   g_qk);
    cudaGetSymbolAddress((void**)&ybar, g_ybar);
    cudaGetSymbolAddress((void**)&wg,   g_wg);
    cudaGetSymbolAddress((void**)&wf,   g_wf);

    cudaFuncSetAttribute(gemm2, cudaFuncAttributeMaxDynamicSharedMemorySize, GEMM_SMEM);

    // P0: fold weights (fp32 exact)
    wg_kernel<<<2048, 256>>>(W_q, W_kv, wg);
    wf_kernel<<<512,  256>>>(W_kv, W_out, wf);

    // K_A: qk[p, h*256+c] = x[p,:] @ Wg   (M=16384, N=2048, K=256)
    gemm2<<<dim3(128, 16), 256, GEMM_SMEM>>>(x, wg, qk, nullptr, 256, 256, 2048, 2048);

    // K_B: dots -> softmax -> ybar
    attn2<<<NPOS, 128>>>(y, qk, ybar);

    // K_C: out = ybar @ Wf + b_out       (M=16384, N=256, K=2048)
    gemm2<<<dim3(128, 2), 256, GEMM_SMEM>>>(ybar, wf, out, b_out, 2048, 2048, 256, 256);
}

// round 3
// speedup vs baseline: 1.6081x; 1.0849x over previous
#include <cuda_runtime.h>
#include <cstdint>

#define NPOS   16384
#define SCALEF 0.125f

// -------- scratch (device globals; no allocation allowed) --------
__device__ float g_qk[(size_t)NPOS * 2048];    // 134 MB
__device__ float g_ybar[(size_t)NPOS * 2048];  // 134 MB
__device__ float g_wg[256 * 2048];             // 2 MB : SCALE * Wq @ Wk^T  (per head)
__device__ float g_wf[2048 * 256];             // 2 MB : Wv @ W_out        (per head)

// ================= precompute kernels (exact fp32) =================
__global__ __launch_bounds__(256)
void wg_kernel(const float* __restrict__ Wq, const float* __restrict__ Wkv,
               float* __restrict__ Wg)
{
    int idx = blockIdx.x * 256 + threadIdx.x;   // 524288 total
    int i = idx >> 11;
    int h = (idx >> 8) & 7;
    int c = idx & 255;
    const float4* a = (const float4*)(Wq  + i * 512  + h * 64);
    const float4* b = (const float4*)(Wkv + c * 1024 + h * 64);
    float s = 0.f;
#pragma unroll
    for (int d = 0; d < 16; d++) {
        float4 u = a[d], v = b[d];
        s += u.x * v.x + u.y * v.y + u.z * v.z + u.w * v.w;
    }
    Wg[idx] = SCALEF * s;
}

__global__ __launch_bounds__(256)
void wf_kernel(const float* __restrict__ Wkv, const float* __restrict__ Wout,
               float* __restrict__ Wf)
{
    int idx = blockIdx.x * 256 + threadIdx.x;   // 131072 total
    int row = idx >> 6;              // h*256+c
    int j = (idx & 63) * 4;
    int h = row >> 8, c = row & 255;
    const float* wv = Wkv + c * 1024 + 512 + h * 64;
    const float* wo = Wout + h * 64 * 256 + j;
    float4 acc = make_float4(0.f, 0.f, 0.f, 0.f);
#pragma unroll 8
    for (int d = 0; d < 64; d++) {
        float s = wv[d];
        float4 o = *(const float4*)(wo + d * 256);
        acc.x = fmaf(s, o.x, acc.x);
        acc.y = fmaf(s, o.y, acc.y);
        acc.z = fmaf(s, o.z, acc.z);
        acc.w = fmaf(s, o.w, acc.w);
    }
    *(float4*)(Wf + row * 256 + j) = acc;
}

// ================= TF32 helpers =================
__device__ __forceinline__ float f2tf(float x) {
    uint32_t u;
    asm("cvt.rna.tf32.f32 %0, %1;" : "=r"(u) : "f"(x));
    return __uint_as_float(u);
}

__device__ __forceinline__ void mma8(float* d, const uint32_t* a, const uint32_t* b) {
    asm volatile(
        "mma.sync.aligned.m16n8k8.row.col.f32.tf32.tf32.f32 "
        "{%0,%1,%2,%3}, {%4,%5,%6,%7}, {%8,%9}, {%0,%1,%2,%3};"
        : "+f"(d[0]), "+f"(d[1]), "+f"(d[2]), "+f"(d[3])
        : "r"(a[0]), "r"(a[1]), "r"(a[2]), "r"(a[3]), "r"(b[0]), "r"(b[1]));
}

__device__ __forceinline__ void cpasync16(uint32_t s, const void* g) {
    asm volatile("cp.async.cg.shared.global [%0], [%1], 16;" :: "r"(s), "l"(g));
}

// ================= TF32 GEMM: cp.async double-buffer, 256 thr =================
#define BM 128
#define BN 128
#define BK 32
#define ASTR 36
#define BSTR 132
#define A_FLOATS (BM * ASTR)
#define B_FLOATS (BK * BSTR)
#define GEMM_SMEM ((2 * A_FLOATS + 2 * B_FLOATS) * 4)

__global__ __launch_bounds__(256, 2)
void gemm2(const float* __restrict__ A, const float* __restrict__ B,
           float* __restrict__ C, const float* __restrict__ bias,
           int K, int lda, int ldb, int ldc)
{
    extern __shared__ float sm[];
    float* As = sm;
    float* Bs = sm + 2 * A_FLOATS;

    const int t = threadIdx.x;
    const int lane = t & 31, wid = t >> 5;
    const int g = lane >> 2, tig = lane & 3;
    const int wm = (wid & 1) * 64;
    const int wn = (wid >> 1) * 32;
    const long long bm = (long long)blockIdx.x * BM;
    const long long bn = (long long)blockIdx.y * BN;

    const int arow = t >> 3, ac4 = t & 7;
    const int brow = t >> 5, bc4 = t & 31;

    const float* Ag = A + (bm + arow) * lda + ac4 * 4;
    const float* Bg = B + (long long)brow * ldb + bn + bc4 * 4;

    uint32_t as_s[2], bs_s[2];
#pragma unroll
    for (int s = 0; s < 2; s++) {
        as_s[s] = (uint32_t)__cvta_generic_to_shared(As + s * A_FLOATS + arow * ASTR + ac4 * 4);
        bs_s[s] = (uint32_t)__cvta_generic_to_shared(Bs + s * B_FLOATS + brow * BSTR + bc4 * 4);
    }

    float acc[4][4][4];
#pragma unroll
    for (int i = 0; i < 4; i++)
#pragma unroll
        for (int j = 0; j < 4; j++)
#pragma unroll
            for (int q = 0; q < 4; q++) acc[i][j][q] = 0.f;

    const int ntiles = K / BK;

#pragma unroll
    for (int i = 0; i < 4; i++) {
        cpasync16(as_s[0] + i * 32 * ASTR * 4, Ag + (long long)(32 * i) * lda);
        cpasync16(bs_s[0] + i * 8 * BSTR * 4,  Bg + (long long)(8 * i) * ldb);
    }
    asm volatile("cp.async.commit_group;");

    for (int it = 0; it < ntiles; it++) {
        const int buf = it & 1;
        if (it + 1 < ntiles) {
            const int nb = buf ^ 1;
            const long long koff = (long long)(it + 1) * BK;
#pragma unroll
            for (int i = 0; i < 4; i++) {
                cpasync16(as_s[nb] + i * 32 * ASTR * 4, Ag + (long long)(32 * i) * lda + koff);
                cpasync16(bs_s[nb] + i * 8 * BSTR * 4,  Bg + (koff + 8 * i) * ldb);
            }
            asm volatile("cp.async.commit_group;");
            asm volatile("cp.async.wait_group 1;");
        } else {
            asm volatile("cp.async.wait_group 0;");
        }
        __syncthreads();

        const float* as = As + buf * A_FLOATS;
        const float* bs = Bs + buf * B_FLOATS;
#pragma unroll
        for (int ks = 0; ks < 4; ks++) {
            const int k0 = ks * 8;
            uint32_t af[4][4], bf[4][2];
#pragma unroll
            for (int mi = 0; mi < 4; mi++) {
                const int r = wm + mi * 16 + g;
                af[mi][0] = __float_as_uint(f2tf(as[r * ASTR + k0 + tig]));
                af[mi][1] = __float_as_uint(f2tf(as[(r + 8) * ASTR + k0 + tig]));
                af[mi][2] = __float_as_uint(f2tf(as[r * ASTR + k0 + tig + 4]));
                af[mi][3] = __float_as_uint(f2tf(as[(r + 8) * ASTR + k0 + tig + 4]));
            }
#pragma unroll
            for (int ni = 0; ni < 4; ni++) {
                const int cn = wn + ni * 8 + g;
                bf[ni][0] = __float_as_uint(f2tf(bs[(k0 + tig) * BSTR + cn]));
                bf[ni][1] = __float_as_uint(f2tf(bs[(k0 + tig + 4) * BSTR + cn]));
            }
#pragma unroll
            for (int mi = 0; mi < 4; mi++)
#pragma unroll
                for (int ni = 0; ni < 4; ni++)
                    mma8(acc[mi][ni], af[mi], bf[ni]);
        }
        __syncthreads();
    }

#pragma unroll
    for (int mi = 0; mi < 4; mi++) {
#pragma unroll
        for (int ni = 0; ni < 4; ni++) {
            const long long r = bm + wm + mi * 16 + g;
            const int cn = (int)bn + wn + ni * 8 + 2 * tig;
            float b0 = bias ? bias[cn] : 0.f;
            float b1 = bias ? bias[cn + 1] : 0.f;
            float2 v0 = make_float2(acc[mi][ni][0] + b0, acc[mi][ni][1] + b1);
            float2 v1 = make_float2(acc[mi][ni][2] + b0, acc[mi][ni][3] + b1);
            *(float2*)(C + r * ldc + cn)       = v0;
            *(float2*)(C + (r + 8) * ldc + cn) = v1;
        }
    }
}

// ================= fused attention core v3: tensor-core dots =================
// dots[m,h] via split-TF32 mma.m16n8k8 (fp32-equivalent accuracy),
// softmax fp32, ybar fp32.
#define YP 260   // stride ≡ 4 (mod 32): bank-conflict-free fragment LDS

__global__ __launch_bounds__(128)
void attn3(const float* __restrict__ y, const float* __restrict__ qk,
           float* __restrict__ ybar)
{
    __shared__ float ys[16 * YP];
    __shared__ float qs[8 * YP];
    __shared__ float part[4][128];   // per-warp dots partials [m*8+h]
    __shared__ float attn_s[128];    // [m][h]

    const int p = blockIdx.x;
    const int t = threadIdx.x;
    const float* yg = y  + (long long)p * 4096;
    const float* qg = qk + (long long)p * 2048;

#pragma unroll
    for (int i = 0; i < 8; i++) {
        int idx4 = i * 128 + t;
        float4 v = *(const float4*)(yg + idx4 * 4);
        int m = idx4 >> 6, c = (idx4 & 63) * 4;
        *(float4*)(ys + m * YP + c) = v;
    }
#pragma unroll
    for (int i = 0; i < 4; i++) {
        int idx4 = i * 128 + t;
        float4 v = *(const float4*)(qg + idx4 * 4);
        int h = idx4 >> 6, c = (idx4 & 63) * 4;
        *(float4*)(qs + h * YP + c) = v;
    }
    __syncthreads();

    const int lane = t & 31, w = t >> 5;
    const int g = lane >> 2, tig = lane & 3;

    // --- dots via mma: warp w covers c in [64w, 64w+64) ---
    float acc[4] = {0.f, 0.f, 0.f, 0.f};
#pragma unroll
    for (int cc = 0; cc < 8; cc++) {
        const int c0 = w * 64 + cc * 8;
        // A fragment (y, 16x8): a0:(g,tig) a1:(g+8,tig) a2:(g,tig+4) a3:(g+8,tig+4)
        float a[4], b[2];
        a[0] = ys[g * YP + c0 + tig];
        a[1] = ys[(g + 8) * YP + c0 + tig];
        a[2] = ys[g * YP + c0 + tig + 4];
        a[3] = ys[(g + 8) * YP + c0 + tig + 4];
        // B fragment (qk, 8kx8n col): b0:(k=tig, n=g) b1:(k=tig+4, n=g)
        b[0] = qs[g * YP + c0 + tig];
        b[1] = qs[g * YP + c0 + tig + 4];

        uint32_t ah[4], al[4], bh[2], bl[2];
#pragma unroll
        for (int i = 0; i < 4; i++) {
            float hi = f2tf(a[i]);
            ah[i] = __float_as_uint(hi);
            al[i] = __float_as_uint(f2tf(a[i] - hi));
        }
#pragma unroll
        for (int i = 0; i < 2; i++) {
            float hi = f2tf(b[i]);
            bh[i] = __float_as_uint(hi);
            bl[i] = __float_as_uint(f2tf(b[i] - hi));
        }
        mma8(acc, ah, bh);
        mma8(acc, al, bh);
        mma8(acc, ah, bl);
    }
    // D fragment: c0:(m=g, h=2tig) c1:(g, 2tig+1) c2:(g+8, 2tig) c3:(g+8, 2tig+1)
    part[w][g * 8 + 2 * tig]           = acc[0];
    part[w][g * 8 + 2 * tig + 1]       = acc[1];
    part[w][(g + 8) * 8 + 2 * tig]     = acc[2];
    part[w][(g + 8) * 8 + 2 * tig + 1] = acc[3];
    __syncthreads();

    const int h = t >> 4, m = t & 15;
    float dot = part[0][m * 8 + h] + part[1][m * 8 + h]
              + part[2][m * 8 + h] + part[3][m * 8 + h];

    // softmax over the 16 lanes sharing h
    float mx = dot;
#pragma unroll
    for (int o = 8; o >= 1; o >>= 1)
        mx = fmaxf(mx, __shfl_xor_sync(0xffffffffu, mx, o));
    float e = __expf(dot - mx);
    float s = e;
#pragma unroll
    for (int o = 8; o >= 1; o >>= 1)
        s += __shfl_xor_sync(0xffffffffu, s, o);
    attn_s[m * 8 + h] = e / s;
    __syncthreads();

    // --- ybar: thread owns 2 c-columns across all 8 heads; y read once ---
    const int c0 = 2 * t;
    float2 acc2[8];
#pragma unroll
    for (int i = 0; i < 8; i++) acc2[i] = make_float2(0.f, 0.f);

#pragma unroll
    for (int mm = 0; mm < 16; mm++) {
        float4 a0 = *(const float4*)(attn_s + mm * 8);
        float4 a1 = *(const float4*)(attn_s + mm * 8 + 4);
        float2 yv = *(const float2*)(ys + mm * YP + c0);
        acc2[0].x = fmaf(a0.x, yv.x, acc2[0].x); acc2[0].y = fmaf(a0.x, yv.y, acc2[0].y);
        acc2[1].x = fmaf(a0.y, yv.x, acc2[1].x); acc2[1].y = fmaf(a0.y, yv.y, acc2[1].y);
        acc2[2].x = fmaf(a0.z, yv.x, acc2[2].x); acc2[2].y = fmaf(a0.z, yv.y, acc2[2].y);
        acc2[3].x = fmaf(a0.w, yv.x, acc2[3].x); acc2[3].y = fmaf(a0.w, yv.y, acc2[3].y);
        acc2[4].x = fmaf(a1.x, yv.x, acc2[4].x); acc2[4].y = fmaf(a1.x, yv.y, acc2[4].y);
        acc2[5].x = fmaf(a1.y, yv.x, acc2[5].x); acc2[5].y = fmaf(a1.y, yv.y, acc2[5].y);
        acc2[6].x = fmaf(a1.z, yv.x, acc2[6].x); acc2[6].y = fmaf(a1.z, yv.y, acc2[6].y);
        acc2[7].x = fmaf(a1.w, yv.x, acc2[7].x); acc2[7].y = fmaf(a1.w, yv.y, acc2[7].y);
    }

    float* op = ybar + (long long)p * 2048 + c0;
#pragma unroll
    for (int hh = 0; hh < 8; hh++)
        *(float2*)(op + hh * 256) = acc2[hh];
}

// ================= launch =================
extern "C" void kernel_launch(void* const* d_in, const int* in_sizes, int n_in,
                              void* d_out, int out_size)
{
    const float* x     = (const float*)d_in[0];
    const float* y     = (const float*)d_in[1];
    const float* W_q   = (const float*)d_in[2];
    const float* W_kv  = (const float*)d_in[3];
    const float* W_out = (const float*)d_in[4];
    const float* b_out = (const float*)d_in[5];
    float* out = (float*)d_out;

    float *qk, *ybar, *wg, *wf;
    cudaGetSymbolAddress((void**)&qk,   g_qk);
    cudaGetSymbolAddress((void**)&ybar, g_ybar);
    cudaGetSymbolAddress((void**)&wg,   g_wg);
    cudaGetSymbolAddress((void**)&wf,   g_wf);

    cudaFuncSetAttribute(gemm2, cudaFuncAttributeMaxDynamicSharedMemorySize, GEMM_SMEM);

    // P0: fold weights (fp32 exact)
    wg_kernel<<<2048, 256>>>(W_q, W_kv, wg);
    wf_kernel<<<512,  256>>>(W_kv, W_out, wf);

    // K_A: qk = x @ Wg   (M=16384, N=2048, K=256)
    gemm2<<<dim3(128, 16), 256, GEMM_SMEM>>>(x, wg, qk, nullptr, 256, 256, 2048, 2048);

    // K_B: dots -> softmax -> ybar
    attn3<<<NPOS, 128>>>(y, qk, ybar);

    // K_C: out = ybar @ Wf + b_out       (M=16384, N=256, K=2048)
    gemm2<<<dim3(128, 2), 256, GEMM_SMEM>>>(ybar, wf, out, b_out, 2048, 2048, 256, 256);
}